// round 17
// baseline (speedup 1.0000x reference)
#include <cuda_runtime.h>

#define NLAYERS 7
#define EPS_F 1e-5f

// Shapes (fixed by setup_inputs): bsz=8, C=8, QL=KL=128, A=8, cross_range=2
// pw / out: [64, 1024, 1024] f32;  conv_w: [7,8,8,1,3]; conv_b: [7,8]; prelu_a: [7]
//
// One CTA per (b, q). Register-resident 7-layer residual conv via __shfl_sync.
// Zero fill is row-sequential float4 stores (dense, incl. band, overwritten
// later in-CTA). Slice schedule spans the WHOLE kernel: slice 0 pre-conv,
// slices 1-6 inside layers 0-5, slice 7 in the epilogue just before the
// single __syncthreads. Epilogue uses one barrier: each thread sums its four
// sPS partials locally (no sInv broadcast buffer, no second barrier).

__device__ __forceinline__ void stcs4(float* p, float4 v) {
    asm volatile("st.global.cs.v4.f32 [%0], {%1,%2,%3,%4};"
                 :: "l"(p), "f"(v.x), "f"(v.y), "f"(v.z), "f"(v.w) : "memory");
}

__global__ __launch_bounds__(256, 5)
void sag_duty(const float* __restrict__ pw,
              const float* __restrict__ conv_w,
              const float* __restrict__ conv_b,
              const float* __restrict__ prelu_a,
              float* __restrict__ out)
{
    __shared__ float4 sW4[NLAYERS][8][8];   // [l][ci][co] = (k0,k1,k2,_)
    __shared__ float  sB [NLAYERS][8];
    __shared__ float  sA [NLAYERS];
    __shared__ float  sPS[4][8][8];         // partial row sums [pp][hh][co]

    const int tid  = threadIdx.x;
    const int lane = tid & 31;
    const int wrp  = tid >> 5;              // warp id 0..7
    const int b = blockIdx.x >> 7;          // batch
    const int i = blockIdx.x & 127;         // query index
    const size_t base = ((size_t)(b * 8) * 1024 + (size_t)i * 8) * 1024;

    // zero-stream base: warp wrp owns row (channel s, agent-row wrp);
    // 8 contiguous 512B warp-stores cover the 4KB row
    float* zrow0 = out + base + (size_t)wrp * 1024 + lane * 4;
    const float4 z = make_float4(0.f, 0.f, 0.f, 0.f);

    // compute roles: slab = pp*8+hh (8 lanes per slab), co = lane&7
    const int co   = tid & 7;
    const int pp   = tid >> 6;
    const int hh   = (tid >> 3) & 7;
    const int doff = (pp < 2) ? (pp - 2) : (pp - 1);  // {-2,-1,1,2}
    const int j    = i + doff;
    const bool pvalid = (j >= 0) && (j < 128);

    // ---- x load issued first ----
    float4 v0 = make_float4(0.f,0.f,0.f,0.f), v1 = v0;
    if (pvalid) {
        const float* srcx = pw +
            ((size_t)((b * 8 + co) * 1024 + (i * 8 + hh)) * 1024 + (size_t)j * 8);
        v0 = *(const float4*)srcx;
        v1 = *(const float4*)(srcx + 4);
    }

    // ---- zero slice 0: channel 0, full 4KB row per warp, sequential ----
    {
        float* p = zrow0;
        #pragma unroll
        for (int g = 0; g < 8; g++) stcs4(p + g * 128, z);
    }

    // ---- conv params -> SMEM ----
    for (int t = tid; t < NLAYERS * 64; t += 256) {
        const int l = t >> 6, rem = t & 63, wco = rem >> 3, wci = rem & 7;
        const float* s = conv_w + ((l * 8 + wco) * 8 + wci) * 3;
        sW4[l][wci][wco] = make_float4(s[0], s[1], s[2], 0.f);
    }
    if (tid < NLAYERS * 8) (&sB[0][0])[tid] = conv_b[tid];
    if (tid < NLAYERS)     sA[tid] = prelu_a[tid];
    __syncthreads();

    float x[8] = {v0.x, v0.y, v0.z, v0.w, v1.x, v1.y, v1.z, v1.w};
    float c[8];
    #pragma unroll
    for (int w = 0; w < 8; w++) c[w] = x[w];

    const int gbase = lane & 24;            // slab group base lane

    // ---- 7-layer residual conv, rolling 3-reg shuffle window ----
    // zero slices 1..6 inside layers 0..5 (layer 6 has none; slice 7 is
    // issued in the epilogue to keep DRAM busy through the tail).
    #pragma unroll 1
    for (int l = 0; l < NLAYERS; l++) {
        const float bias = sB[l][co];
        float acc[8];
        #pragma unroll
        for (int w = 0; w < 8; w++) acc[w] = bias;

        #pragma unroll
        for (int ci = 0; ci < 8; ci++) {
            const float4 wv = sW4[l][ci][co];
            const int src = gbase | ci;
            float ra = __shfl_sync(0xffffffffu, c[0], src);
            float rb = __shfl_sync(0xffffffffu, c[1], src);
            acc[0] += wv.y * ra + wv.z * rb;
            #pragma unroll
            for (int w = 1; w < 7; w++) {
                const float rc = __shfl_sync(0xffffffffu, c[w + 1], src);
                acc[w] += wv.x * ra + wv.y * rb + wv.z * rc;
                ra = rb; rb = rc;
            }
            acc[7] += wv.x * ra + wv.y * rb;
        }

        if (l < 6) {
            float* p = zrow0 + (size_t)(l + 1) * (1024 * 1024);
            #pragma unroll
            for (int g = 0; g < 8; g++) stcs4(p + g * 128, z);
        }

        const float pa = sA[l];
        #pragma unroll
        for (int w = 0; w < 8; w++) {
            const float y = (acc[w] >= 0.f) ? acc[w] : pa * acc[w];
            c[w] = y + c[w];                // residual, in place
        }
    }

    // ---- we = exp(relu(x - sigmoid(conv)))-1, masked; reuse x[] ----
    float partial = 0.f;
    #pragma unroll
    for (int w = 0; w < 8; w++) {
        const float sg = 1.f / (1.f + __expf(-c[w]));
        float sp = fmaxf(x[w] - sg, 0.f);
        if (hh == w) sp = 0.f;              // self mask
        float v = __expf(sp) - 1.f;         // sp >= 0
        if (!pvalid) v = 0.f;
        x[w] = v;
        partial += v;
    }
    sPS[pp][hh][co] = partial;

    // ---- zero slice 7 (channel 7): fills the epilogue's store gap ----
    {
        float* p = zrow0 + (size_t)7 * (1024 * 1024);
        #pragma unroll
        for (int g = 0; g < 8; g++) stcs4(p + g * 128, z);
    }

    __syncthreads();   // sPS visible + orders zero stores before band overwrite

    // ---- per-thread row-sum + band store (no second barrier) ----
    if (pvalid) {
        const float s = sPS[0][hh][co] + sPS[1][hh][co]
                      + sPS[2][hh][co] + sPS[3][hh][co];
        const float inv = 1.f / (s + EPS_F);
        float* dst = out +
            ((size_t)((b * 8 + co) * 1024 + (i * 8 + hh)) * 1024 + (size_t)j * 8);
        stcs4(dst,     make_float4(x[0]*inv, x[1]*inv, x[2]*inv, x[3]*inv));
        stcs4(dst + 4, make_float4(x[4]*inv, x[5]*inv, x[6]*inv, x[7]*inv));
    }
}

extern "C" void kernel_launch(void* const* d_in, const int* in_sizes, int n_in,
                              void* d_out, int out_size) {
    const float* pw = (const float*)d_in[0];
    const float* cw = (const float*)d_in[1];
    const float* cb = (const float*)d_in[2];
    const float* pa = (const float*)d_in[3];
    sag_duty<<<1024, 256>>>(pw, cw, cb, pa, (float*)d_out);
}